// round 1
// baseline (speedup 1.0000x reference)
#include <cuda_runtime.h>
#include <cstdint>

#define Bq 16
#define Nq 4096
#define Sq 1024
#define Kq 32
#define NEq (Bq*Sq*Kq)          // 524288 rows through the MLP
#define OUT_PTS (Bq*Sq*3)       // offset of new_points in d_out

// ---------------- scratch (device globals; no allocations allowed) ----------------
__device__ float  g_sqn[Bq*Nq];            // |xyz|^2 per point (exact left-fold)
__device__ int    g_fps[Bq*Sq];            // FPS indices
__device__ float  g_newxyz[Bq*Sq*3];       // sampled centroids
__device__ int    g_grp[Bq*Sq*Kq];         // ball-query neighbor indices
__device__ float  g_y0[(size_t)NEq*64];    // layer0 pre-BN output
__device__ float  g_y1[(size_t)NEq*64];    // layer1 pre-BN output
__device__ float  g_y2[(size_t)NEq*128];   // layer2 pre-BN output
__device__ double g_part[(size_t)2*128*16384]; // per-block BN partial sums / sumsq
__device__ float  g_scale[384];            // BN fused scale  per layer (off 0/128/256)
__device__ float  g_shift[384];            // BN fused shift

// ---------------- prep: per-point squared norms (exact, no FMA) ----------------
__global__ void k_prep(const float* __restrict__ xyz) {
    int i = blockIdx.x * blockDim.x + threadIdx.x;
    if (i < Bq*Nq) {
        float x = xyz[3*i], y = xyz[3*i+1], z = xyz[3*i+2];
        g_sqn[i] = __fadd_rn(__fadd_rn(__fmul_rn(x,x), __fmul_rn(y,y)), __fmul_rn(z,z));
    }
}

// ---------------- FPS: 1 block per batch, dist array in registers ----------------
__global__ void __launch_bounds__(512) k_fps(const float* __restrict__ xyz) {
    const int b = blockIdx.x;
    const int t = threadIdx.x;
    const float* xb = xyz + b*Nq*3;
    float px[8], py[8], pz[8], dd[8];
    #pragma unroll
    for (int j = 0; j < 8; j++) {
        int p = t + j*512;
        px[j] = xb[3*p]; py[j] = xb[3*p+1]; pz[j] = xb[3*p+2];
        dd[j] = 1e10f;
    }
    __shared__ float swv[16];
    __shared__ int   swi[16];
    __shared__ int   sfar;
    int far = 0;
    for (int i = 0; i < Sq; i++) {
        if (t == 0) g_fps[b*Sq + i] = far;
        float cx = xb[3*far], cy = xb[3*far+1], cz = xb[3*far+2];
        float bv = -1.0f; int bi = 0;
        #pragma unroll
        for (int j = 0; j < 8; j++) {
            float dx = __fsub_rn(px[j], cx);
            float dy = __fsub_rn(py[j], cy);
            float dz = __fsub_rn(pz[j], cz);
            float d  = __fadd_rn(__fadd_rn(__fmul_rn(dx,dx), __fmul_rn(dy,dy)), __fmul_rn(dz,dz));
            float nd = fminf(dd[j], d);
            dd[j] = nd;
            if (nd > bv) { bv = nd; bi = t + j*512; }   // ascending idx -> strict > keeps lowest
        }
        #pragma unroll
        for (int off = 16; off; off >>= 1) {
            float ov = __shfl_down_sync(0xffffffffu, bv, off);
            int   oi = __shfl_down_sync(0xffffffffu, bi, off);
            if (ov > bv || (ov == bv && oi < bi)) { bv = ov; bi = oi; }
        }
        if ((t & 31) == 0) { swv[t>>5] = bv; swi[t>>5] = bi; }
        __syncthreads();
        if (t == 0) {
            float mv = swv[0]; int mi = swi[0];
            #pragma unroll
            for (int w = 1; w < 16; w++) {
                float ov = swv[w]; int oi = swi[w];
                if (ov > mv || (ov == mv && oi < mi)) { mv = ov; mi = oi; }
            }
            sfar = mi;
        }
        __syncthreads();
        far = sfar;
    }
}

// ---------------- gather centroids; write first output chunk ----------------
__global__ void k_newxyz(const float* __restrict__ xyz, float* __restrict__ out) {
    int i = blockIdx.x * blockDim.x + threadIdx.x;
    if (i >= Bq*Sq) return;
    int b = i >> 10;
    int f = g_fps[i];
    float x = xyz[(b*Nq+f)*3+0], y = xyz[(b*Nq+f)*3+1], z = xyz[(b*Nq+f)*3+2];
    g_newxyz[3*i+0] = x; g_newxyz[3*i+1] = y; g_newxyz[3*i+2] = z;
    out[3*i+0] = x; out[3*i+1] = y; out[3*i+2] = z;
}

// ---------------- ball query: compact in-ball candidates, 32 argmin passes ----------------
__global__ void __launch_bounds__(128) k_ball(const float* __restrict__ xyz) {
    const int q = blockIdx.x;
    const int b = q >> 10;
    const int t = threadIdx.x;
    __shared__ float cd[Nq];
    __shared__ int   ci[Nq];
    __shared__ int   scnt;
    __shared__ float rwv[4];
    __shared__ int   rwi[4], rwp[4];
    __shared__ int   ssel[Kq];
    if (t == 0) scnt = 0;
    __syncthreads();
    float cx = g_newxyz[3*q], cy = g_newxyz[3*q+1], cz = g_newxyz[3*q+2];
    float sa = __fadd_rn(__fadd_rn(__fmul_rn(cx,cx), __fmul_rn(cy,cy)), __fmul_rn(cz,cz));
    const float* xb = xyz + b*Nq*3;
    const float* sq = g_sqn + b*Nq;
    for (int n = t; n < Nq; n += 128) {
        float x = xb[3*n], y = xb[3*n+1], z = xb[3*n+2];
        float dot = __fadd_rn(__fadd_rn(__fmul_rn(x,cx), __fmul_rn(y,cy)), __fmul_rn(z,cz));
        float d = __fsub_rn(__fadd_rn(sa, sq[n]), __fmul_rn(2.0f, dot));
        if (d <= 0.04f) {                   // in-ball  <=>  NOT masked in reference
            int p = atomicAdd(&scnt, 1);
            cd[p] = d; ci[p] = n;
        }
    }
    __syncthreads();
    const int cnt = scnt;                   // >= 1 always (self distance is exactly 0)
    const int m = cnt < Kq ? cnt : Kq;
    for (int j = 0; j < m; j++) {
        float bv = 3.4e38f; int bi = 0x7fffffff, bp = -1;
        for (int p = t; p < cnt; p += 128) {
            float v = cd[p]; int ii = ci[p];
            if (v < bv || (v == bv && ii < bi)) { bv = v; bi = ii; bp = p; }
        }
        #pragma unroll
        for (int off = 16; off; off >>= 1) {
            float ov = __shfl_down_sync(0xffffffffu, bv, off);
            int   oi = __shfl_down_sync(0xffffffffu, bi, off);
            int   op = __shfl_down_sync(0xffffffffu, bp, off);
            if (ov < bv || (ov == bv && oi < bi)) { bv = ov; bi = oi; bp = op; }
        }
        if ((t & 31) == 0) { rwv[t>>5] = bv; rwi[t>>5] = bi; rwp[t>>5] = bp; }
        __syncthreads();
        if (t == 0) {
            float mv = rwv[0]; int mi = rwi[0], mp = rwp[0];
            #pragma unroll
            for (int w = 1; w < 4; w++) {
                if (rwv[w] < mv || (rwv[w] == mv && rwi[w] < mi)) { mv = rwv[w]; mi = rwi[w]; mp = rwp[w]; }
            }
            ssel[j] = mi;
            cd[mp] = 3.4e38f;
        }
        __syncthreads();
    }
    if (t < Kq) {
        g_grp[q*Kq + t] = (t < m) ? ssel[t] : ssel[0];  // out-of-ball slots -> nearest
    }
}

// ---------------- layer0: gather + concat + GEMM [32x67]x[67x64] + BN partials ----------------
__global__ void __launch_bounds__(256) k_layer0(const float* __restrict__ xyz,
                                                const float* __restrict__ points,
                                                const float* __restrict__ W,
                                                const float* __restrict__ bias) {
    const int q = blockIdx.x;
    const int b = q >> 10;
    const int t = threadIdx.x;
    __shared__ __align__(16) float xs[67*33];   // col-major, padded (conflict-free)
    __shared__ __align__(16) float Wt[67*64];   // [c][o]
    for (int i = t; i < 67*64; i += 256) Wt[i] = W[(i & 63)*67 + (i >> 6)];
    const float cx = g_newxyz[3*q], cy = g_newxyz[3*q+1], cz = g_newxyz[3*q+2];
    for (int i = t; i < 32*67; i += 256) {
        int r = i / 67, c = i - r*67;
        int g = g_grp[q*32 + r];
        float v;
        if (c < 3) {
            v = xyz[(b*Nq + g)*3 + c] - (c == 0 ? cx : (c == 1 ? cy : cz));
        } else {
            v = points[(size_t)(b*Nq + g)*64 + (c - 3)];
        }
        xs[c*33 + r] = v;
    }
    __syncthreads();
    const int r0 = (t & 15)*2, o0 = (t >> 4)*4;
    float a0[4], a1[4];
    #pragma unroll
    for (int u = 0; u < 4; u++) { a0[u] = bias[o0+u]; a1[u] = a0[u]; }
    for (int c = 0; c < 67; c++) {
        float x0 = xs[c*33 + r0], x1 = xs[c*33 + r0 + 1];
        float4 wv = *(const float4*)&Wt[c*64 + o0];
        a0[0] = fmaf(x0, wv.x, a0[0]);  a1[0] = fmaf(x1, wv.x, a1[0]);
        a0[1] = fmaf(x0, wv.y, a0[1]);  a1[1] = fmaf(x1, wv.y, a1[1]);
        a0[2] = fmaf(x0, wv.z, a0[2]);  a1[2] = fmaf(x1, wv.z, a1[2]);
        a0[3] = fmaf(x0, wv.w, a0[3]);  a1[3] = fmaf(x1, wv.w, a1[3]);
    }
    size_t base = ((size_t)q*32 + r0)*64 + o0;
    *(float4*)&g_y0[base]      = make_float4(a0[0], a0[1], a0[2], a0[3]);
    *(float4*)&g_y0[base + 64] = make_float4(a1[0], a1[1], a1[2], a1[3]);
    #pragma unroll
    for (int u = 0; u < 4; u++) {
        float s  = a0[u] + a1[u];
        float s2 = a0[u]*a0[u] + a1[u]*a1[u];
        #pragma unroll
        for (int off = 8; off; off >>= 1) {
            s  += __shfl_down_sync(0xffffffffu, s,  off, 16);
            s2 += __shfl_down_sync(0xffffffffu, s2, off, 16);
        }
        if ((t & 15) == 0) {
            g_part[(size_t)(o0+u)*16384 + q]       = (double)s;
            g_part[(size_t)(128+o0+u)*16384 + q]   = (double)s2;
        }
    }
}

// ---------------- BN finalize: fixed-order deterministic reduction ----------------
__global__ void __launch_bounds__(256) k_fin(const float* __restrict__ ga,
                                             const float* __restrict__ be, int off) {
    const int ch = blockIdx.x;
    const int t = threadIdx.x;
    double s = 0.0, s2 = 0.0;
    const double* p0 = g_part + (size_t)ch*16384;
    const double* p1 = g_part + (size_t)(128+ch)*16384;
    for (int i = t; i < 16384; i += 256) { s += p0[i]; s2 += p1[i]; }
    __shared__ double sh[256], sh2[256];
    sh[t] = s; sh2[t] = s2; __syncthreads();
    for (int o = 128; o; o >>= 1) {
        if (t < o) { sh[t] += sh[t+o]; sh2[t] += sh2[t+o]; }
        __syncthreads();
    }
    if (t == 0) {
        double mu  = sh[0]  / (double)NEq;
        double var = sh2[0] / (double)NEq - mu*mu;
        if (var < 0.0) var = 0.0;
        double sc = (double)ga[ch] / sqrt(var + 1e-5);
        g_scale[off+ch] = (float)sc;
        g_shift[off+ch] = (float)((double)be[ch] - mu*sc);
    }
}

// ---------------- layers 1/2: BN+ReLU on read, GEMM, BN partials ----------------
template<int L>
__global__ void __launch_bounds__(256) k_layerN(const float* __restrict__ W,
                                                const float* __restrict__ bias) {
    constexpr int COUT = (L == 2) ? 128 : 64;
    constexpr int CPT  = COUT / 16;
    const float* yin = (L == 1) ? g_y0 : g_y1;
    float* yout      = (L == 1) ? g_y1 : g_y2;
    const int soff   = (L == 1) ? 0 : 128;
    const int q = blockIdx.x;
    const int t = threadIdx.x;
    __shared__ __align__(16) float xs[64*33];
    __shared__ __align__(16) float Wt[64*COUT];
    for (int i = t; i < 64*COUT; i += 256) Wt[i] = W[(i % COUT)*64 + (i / COUT)];
    for (int i = t; i < 32*64; i += 256) {
        int r = i >> 6, c = i & 63;
        float v = yin[((size_t)q*32 + r)*64 + c];
        v = fmaf(g_scale[soff+c], v, g_shift[soff+c]);
        xs[c*33 + r] = fmaxf(v, 0.0f);
    }
    __syncthreads();
    const int r0 = (t & 15)*2, o0 = (t >> 4)*CPT;
    float a0[CPT], a1[CPT];
    #pragma unroll
    for (int u = 0; u < CPT; u++) { a0[u] = bias[o0+u]; a1[u] = a0[u]; }
    for (int c = 0; c < 64; c++) {
        float x0 = xs[c*33 + r0], x1 = xs[c*33 + r0 + 1];
        #pragma unroll
        for (int u = 0; u < CPT; u += 4) {
            float4 wv = *(const float4*)&Wt[c*COUT + o0 + u];
            a0[u+0] = fmaf(x0, wv.x, a0[u+0]);  a1[u+0] = fmaf(x1, wv.x, a1[u+0]);
            a0[u+1] = fmaf(x0, wv.y, a0[u+1]);  a1[u+1] = fmaf(x1, wv.y, a1[u+1]);
            a0[u+2] = fmaf(x0, wv.z, a0[u+2]);  a1[u+2] = fmaf(x1, wv.z, a1[u+2]);
            a0[u+3] = fmaf(x0, wv.w, a0[u+3]);  a1[u+3] = fmaf(x1, wv.w, a1[u+3]);
        }
    }
    size_t base = ((size_t)q*32 + r0)*COUT + o0;
    #pragma unroll
    for (int u = 0; u < CPT; u += 4) {
        *(float4*)&yout[base + u]        = make_float4(a0[u], a0[u+1], a0[u+2], a0[u+3]);
        *(float4*)&yout[base + COUT + u] = make_float4(a1[u], a1[u+1], a1[u+2], a1[u+3]);
    }
    #pragma unroll
    for (int u = 0; u < CPT; u++) {
        float s  = a0[u] + a1[u];
        float s2 = a0[u]*a0[u] + a1[u]*a1[u];
        #pragma unroll
        for (int off = 8; off; off >>= 1) {
            s  += __shfl_down_sync(0xffffffffu, s,  off, 16);
            s2 += __shfl_down_sync(0xffffffffu, s2, off, 16);
        }
        if ((t & 15) == 0) {
            g_part[(size_t)(o0+u)*16384 + q]     = (double)s;
            g_part[(size_t)(128+o0+u)*16384 + q] = (double)s2;
        }
    }
}

// ---------------- final BN+ReLU fused into K-max-pool ----------------
__global__ void __launch_bounds__(128) k_maxpool(float* __restrict__ out) {
    const int q = blockIdx.x;
    const int o = threadIdx.x;
    const float sc = g_scale[256 + o], sh = g_shift[256 + o];
    float m = 0.0f;                          // ReLU floor: max over relu == max(0, max y)
    const float* base = g_y2 + (size_t)q*32*128 + o;
    #pragma unroll 8
    for (int k = 0; k < 32; k++) {
        m = fmaxf(m, fmaf(sc, base[(size_t)k*128], sh));
    }
    out[OUT_PTS + (size_t)q*128 + o] = m;
}

// ---------------- launch ----------------
extern "C" void kernel_launch(void* const* d_in, const int* in_sizes, int n_in,
                              void* d_out, int out_size) {
    (void)in_sizes; (void)n_in; (void)out_size;
    const float* xyz    = (const float*)d_in[0];
    const float* points = (const float*)d_in[1];
    const float* W0  = (const float*)d_in[2];
    const float* b0  = (const float*)d_in[3];
    const float* g0  = (const float*)d_in[4];
    const float* bt0 = (const float*)d_in[5];
    const float* W1  = (const float*)d_in[6];
    const float* b1  = (const float*)d_in[7];
    const float* g1  = (const float*)d_in[8];
    const float* bt1 = (const float*)d_in[9];
    const float* W2  = (const float*)d_in[10];
    const float* b2  = (const float*)d_in[11];
    const float* g2  = (const float*)d_in[12];
    const float* bt2 = (const float*)d_in[13];
    float* out = (float*)d_out;

    k_prep<<<(Bq*Nq + 255)/256, 256>>>(xyz);
    k_fps<<<Bq, 512>>>(xyz);
    k_newxyz<<<(Bq*Sq + 255)/256, 256>>>(xyz, out);
    k_ball<<<Bq*Sq, 128>>>(xyz);

    k_layer0<<<Bq*Sq, 256>>>(xyz, points, W0, b0);
    k_fin<<<64, 256>>>(g0, bt0, 0);
    k_layerN<1><<<Bq*Sq, 256>>>(W1, b1);
    k_fin<<<64, 256>>>(g1, bt1, 128);
    k_layerN<2><<<Bq*Sq, 256>>>(W2, b2);
    k_fin<<<128, 256>>>(g2, bt2, 256);
    k_maxpool<<<Bq*Sq, 128>>>(out);
}

// round 2
// speedup vs baseline: 1.9375x; 1.9375x over previous
#include <cuda_runtime.h>
#include <cstdint>

#define Bq 16
#define Nq 4096
#define Sq 1024
#define Kq 32
#define NQ (Bq*Sq)          // 16384 queries
#define NP (Bq*Nq)          // 65536 points
#define NEq (NQ*Kq)         // 524288 rows
#define OUT_PTS (NQ*3)
#define XS_PAD 132

// ---------------- scratch ----------------
__device__ float  g_sqn[NP];
__device__ float  g_newxyz[NQ*3];
__device__ int    g_grp[NEq];
__device__ float  g_pf[(size_t)NP*64];        // point features (layer0 w/o geom), 16MB
__device__ float  g_y1[(size_t)NEq*64];       // layer1 pre-BN output, 134MB
__device__ float  g_maxv[(size_t)NQ*128];     // layer2 per-query max over K
__device__ float  g_minv[(size_t)NQ*128];
__device__ double g_part[(size_t)256*8192];   // BN partials [ch | 128+ch][block]
__device__ float  g_scale[384];
__device__ float  g_shift[384];

// ---------------- prep: |xyz|^2 exact left-fold ----------------
__global__ void k_prep(const float* __restrict__ xyz) {
    int i = blockIdx.x * blockDim.x + threadIdx.x;
    if (i < NP) {
        float x = xyz[3*i], y = xyz[3*i+1], z = xyz[3*i+2];
        g_sqn[i] = __fadd_rn(__fadd_rn(__fmul_rn(x,x), __fmul_rn(y,y)), __fmul_rn(z,z));
    }
}

// ---------------- FPS: packed-u64 two-level reduce; writes new_xyz directly ----------------
__global__ void __launch_bounds__(512) k_fps(const float* __restrict__ xyz,
                                             float* __restrict__ out) {
    const int b = blockIdx.x;
    const int t = threadIdx.x;
    const int lane = t & 31, wid = t >> 5;
    const float* xb = xyz + b*Nq*3;
    float px[8], py[8], pz[8], dd[8];
    #pragma unroll
    for (int j = 0; j < 8; j++) {
        int p = t + j*512;
        px[j] = xb[3*p]; py[j] = xb[3*p+1]; pz[j] = xb[3*p+2];
        dd[j] = 1e10f;
    }
    __shared__ unsigned long long swk[16];
    __shared__ int sfar;
    int far = 0;
    for (int i = 0; i < Sq; i++) {
        float cx = xb[3*far], cy = xb[3*far+1], cz = xb[3*far+2];
        if (t == 0) {
            int o = (b*Sq + i)*3;
            g_newxyz[o] = cx; g_newxyz[o+1] = cy; g_newxyz[o+2] = cz;
            out[o] = cx; out[o+1] = cy; out[o+2] = cz;
        }
        float bv = -1.0f; int bi = 0;
        #pragma unroll
        for (int j = 0; j < 8; j++) {
            float dx = __fsub_rn(px[j], cx);
            float dy = __fsub_rn(py[j], cy);
            float dz = __fsub_rn(pz[j], cz);
            float d  = __fadd_rn(__fadd_rn(__fmul_rn(dx,dx), __fmul_rn(dy,dy)), __fmul_rn(dz,dz));
            float nd = fminf(dd[j], d);
            dd[j] = nd;
            if (nd > bv) { bv = nd; bi = t + j*512; }   // strict > keeps lowest idx in-thread
        }
        // dd >= 0 always -> float bits are order-preserving; ~idx breaks ties toward low idx
        unsigned long long key = ((unsigned long long)__float_as_uint(bv) << 32)
                               | (unsigned)(~(unsigned)bi);
        #pragma unroll
        for (int off = 16; off; off >>= 1) {
            unsigned long long o = __shfl_down_sync(0xffffffffu, key, off);
            if (o > key) key = o;
        }
        if (lane == 0) swk[wid] = key;
        __syncthreads();
        if (t < 16) {
            unsigned long long k2 = swk[t];
            #pragma unroll
            for (int off = 8; off; off >>= 1) {
                unsigned long long o = __shfl_down_sync(0x0000ffffu, k2, off, 16);
                if (o > k2) k2 = o;
            }
            if (t == 0) sfar = (int)(~(unsigned)k2);
        }
        __syncthreads();
        far = sfar;
    }
}

// ---------------- ball query: compact candidates, O(cnt^2) rank selection ----------------
__global__ void __launch_bounds__(128) k_ball(const float* __restrict__ xyz) {
    const int q = blockIdx.x;
    const int b = q >> 10;
    const int t = threadIdx.x;
    __shared__ unsigned long long ck[Nq];
    __shared__ int scnt;
    __shared__ int ssel[Kq];
    if (t == 0) scnt = 0;
    __syncthreads();
    float cx = g_newxyz[3*q], cy = g_newxyz[3*q+1], cz = g_newxyz[3*q+2];
    float sa = __fadd_rn(__fadd_rn(__fmul_rn(cx,cx), __fmul_rn(cy,cy)), __fmul_rn(cz,cz));
    const float* xb = xyz + b*Nq*3;
    const float* sq = g_sqn + b*Nq;
    for (int n = t; n < Nq; n += 128) {
        float x = xb[3*n], y = xb[3*n+1], z = xb[3*n+2];
        float dot = __fadd_rn(__fadd_rn(__fmul_rn(x,cx), __fmul_rn(y,cy)), __fmul_rn(z,cz));
        float d = __fsub_rn(__fadd_rn(sa, sq[n]), __fmul_rn(2.0f, dot));
        if (d <= 0.04f) {
            // monotonic float->uint transform (d can round slightly negative)
            unsigned ub = __float_as_uint(d);
            ub = ((int)ub < 0) ? ~ub : (ub | 0x80000000u);
            int p = atomicAdd(&scnt, 1);
            ck[p] = ((unsigned long long)ub << 32) | (unsigned)n;
        }
    }
    __syncthreads();
    const int cnt = scnt;                 // >= 1 (self distance exactly 0)
    const int m = cnt < Kq ? cnt : Kq;
    for (int p = t; p < cnt; p += 128) {
        unsigned long long mk = ck[p];
        int r = 0;
        for (int j = 0; j < cnt; j++) r += (ck[j] < mk);   // broadcast LDS
        if (r < Kq) ssel[r] = (int)(unsigned)mk;
    }
    __syncthreads();
    if (t < Kq) g_grp[q*Kq + t] = ssel[t < m ? t : 0];
}

// ---------------- point-feature GEMM: pf[n][o] = sum_c points[n][c] * W0[o][3+c] ----------------
__global__ void __launch_bounds__(128) k_pf(const float* __restrict__ points,
                                            const float* __restrict__ W0) {
    extern __shared__ float sm[];
    float* xs = sm;                   // [64][XS_PAD]
    float* Wt = sm + 64*XS_PAD;       // [64][64]
    const int t = threadIdx.x;
    const int blk = blockIdx.x;
    for (int i = t; i < 4096; i += 128) Wt[i] = W0[(i & 63)*67 + 3 + (i >> 6)];
    const float4* pts4 = (const float4*)points;
    #pragma unroll
    for (int jj = 0; jj < 16; jj++) {
        int idx = t + jj*128;
        int r = idx >> 4, c4 = idx & 15;
        float4 v = pts4[(size_t)(blk*128 + r)*16 + c4];
        xs[(4*c4+0)*XS_PAD + r] = v.x;
        xs[(4*c4+1)*XS_PAD + r] = v.y;
        xs[(4*c4+2)*XS_PAD + r] = v.z;
        xs[(4*c4+3)*XS_PAD + r] = v.w;
    }
    __syncthreads();
    const int r0 = (t & 15)*8, o0 = (t >> 4)*8;
    float acc[8][8];
    #pragma unroll
    for (int i = 0; i < 8; i++)
        #pragma unroll
        for (int j = 0; j < 8; j++) acc[i][j] = 0.0f;
    for (int c = 0; c < 64; c++) {
        float4 xa = *(const float4*)&xs[c*XS_PAD + r0];
        float4 xc = *(const float4*)&xs[c*XS_PAD + r0 + 4];
        float4 wa = *(const float4*)&Wt[c*64 + o0];
        float4 wb = *(const float4*)&Wt[c*64 + o0 + 4];
        float xr[8] = {xa.x,xa.y,xa.z,xa.w,xc.x,xc.y,xc.z,xc.w};
        float wr[8] = {wa.x,wa.y,wa.z,wa.w,wb.x,wb.y,wb.z,wb.w};
        #pragma unroll
        for (int i = 0; i < 8; i++)
            #pragma unroll
            for (int j = 0; j < 8; j++) acc[i][j] = fmaf(xr[i], wr[j], acc[i][j]);
    }
    #pragma unroll
    for (int i = 0; i < 8; i++) {
        size_t base = ((size_t)(blk*128 + r0 + i))*64 + o0;
        *(float4*)&g_pf[base]   = make_float4(acc[i][0],acc[i][1],acc[i][2],acc[i][3]);
        *(float4*)&g_pf[base+4] = make_float4(acc[i][4],acc[i][5],acc[i][6],acc[i][7]);
    }
}

// ---------------- layer0 stats: recompute y0 on the fly, BN0 partials only ----------------
__global__ void __launch_bounds__(256) k_l0stats(const float* __restrict__ xyz,
                                                 const float* __restrict__ W0,
                                                 const float* __restrict__ b0) {
    __shared__ int   sgp[256];
    __shared__ float sdx[256], sdy[256], sdz[256];
    __shared__ float swx[64], swy[64], swz[64], sb[64];
    __shared__ double shs[256], shq[256];
    const int t = threadIdx.x;
    const int blk = blockIdx.x;
    if (t < 64) {
        swx[t] = W0[t*67+0]; swy[t] = W0[t*67+1]; swz[t] = W0[t*67+2]; sb[t] = b0[t];
    }
    {
        int R = blk*256 + t;
        int q = R >> 5, b = q >> 10;
        int gp = b*Nq + g_grp[R];
        sgp[t] = gp;
        sdx[t] = __fsub_rn(xyz[gp*3+0], g_newxyz[3*q+0]);
        sdy[t] = __fsub_rn(xyz[gp*3+1], g_newxyz[3*q+1]);
        sdz[t] = __fsub_rn(xyz[gp*3+2], g_newxyz[3*q+2]);
    }
    __syncthreads();
    const int ch = t & 63, rg = t >> 6;
    float wx = swx[ch], wy = swy[ch], wz = swz[ch], bb = sb[ch];
    float s = 0.0f, s2 = 0.0f;
    for (int j = 0; j < 64; j++) {
        int r = rg*64 + j;
        float pfv = g_pf[(size_t)sgp[r]*64 + ch];
        float y = pfv + fmaf(sdx[r], wx, fmaf(sdy[r], wy, fmaf(sdz[r], wz, bb)));
        s += y; s2 = fmaf(y, y, s2);
    }
    shs[t] = (double)s; shq[t] = (double)s2;
    __syncthreads();
    if (t < 64) {
        double S = (shs[t] + shs[t+64]) + (shs[t+128] + shs[t+192]);
        double Q = (shq[t] + shq[t+64]) + (shq[t+128] + shq[t+192]);
        g_part[(size_t)t*8192 + blk]       = S;
        g_part[(size_t)(128+t)*8192 + blk] = Q;
    }
}

// ---------------- BN finalize ----------------
__global__ void __launch_bounds__(256) k_fin(const float* __restrict__ ga,
                                             const float* __restrict__ be,
                                             int off, int nblk) {
    const int ch = blockIdx.x;
    const int t = threadIdx.x;
    double s = 0.0, s2 = 0.0;
    const double* p0 = g_part + (size_t)ch*8192;
    const double* p1 = g_part + (size_t)(128+ch)*8192;
    for (int i = t; i < nblk; i += 256) { s += p0[i]; s2 += p1[i]; }
    __shared__ double sh[256], sh2[256];
    sh[t] = s; sh2[t] = s2; __syncthreads();
    for (int o = 128; o; o >>= 1) {
        if (t < o) { sh[t] += sh[t+o]; sh2[t] += sh2[t+o]; }
        __syncthreads();
    }
    if (t == 0) {
        double mu  = sh[0]  / (double)NEq;
        double var = sh2[0] / (double)NEq - mu*mu;
        if (var < 0.0) var = 0.0;
        double sc = (double)ga[ch] / sqrt(var + 1e-5);
        g_scale[off+ch] = (float)sc;
        g_shift[off+ch] = (float)((double)be[ch] - mu*sc);
    }
}

// ---------------- layer1: recompute y0 + BN0 + ReLU, GEMM 128x64x64, write y1 + partials ----------------
__global__ void __launch_bounds__(128) k_layer1(const float* __restrict__ xyz,
                                                const float* __restrict__ W0,
                                                const float* __restrict__ b0,
                                                const float* __restrict__ W1,
                                                const float* __restrict__ b1) {
    extern __shared__ float sm[];
    float* xs  = sm;                   // [64][XS_PAD]
    float* Wt  = sm + 64*XS_PAD;       // [64][64]
    float* swx = Wt + 4096;
    float* swy = swx + 64; float* swz = swy + 64; float* sb = swz + 64;
    float* ssc = sb + 64;  float* ssh = ssc + 64;
    const int t = threadIdx.x;
    const int blk = blockIdx.x;
    for (int i = t; i < 4096; i += 128) Wt[i] = W1[(i & 63)*64 + (i >> 6)];
    if (t < 64) {
        swx[t] = W0[t*67+0]; swy[t] = W0[t*67+1]; swz[t] = W0[t*67+2];
        sb[t] = b0[t]; ssc[t] = g_scale[t]; ssh[t] = g_shift[t];
    }
    int R = blk*128 + t;
    int q = R >> 5, b = q >> 10;
    int gp = b*Nq + g_grp[R];
    float dx = __fsub_rn(xyz[gp*3+0], g_newxyz[3*q+0]);
    float dy = __fsub_rn(xyz[gp*3+1], g_newxyz[3*q+1]);
    float dz = __fsub_rn(xyz[gp*3+2], g_newxyz[3*q+2]);
    __syncthreads();
    const float4* pfv4 = (const float4*)g_pf;
    #pragma unroll
    for (int c4 = 0; c4 < 16; c4++) {
        float4 p = pfv4[(size_t)gp*16 + c4];
        float pv[4] = {p.x, p.y, p.z, p.w};
        #pragma unroll
        for (int k2 = 0; k2 < 4; k2++) {
            int c = c4*4 + k2;
            float y = pv[k2] + fmaf(dx, swx[c], fmaf(dy, swy[c], fmaf(dz, swz[c], sb[c])));
            xs[c*XS_PAD + t] = fmaxf(fmaf(ssc[c], y, ssh[c]), 0.0f);
        }
    }
    __syncthreads();
    const int r0 = (t & 15)*8, o0 = (t >> 4)*8;
    float acc[8][8];
    #pragma unroll
    for (int j = 0; j < 8; j++) {
        float bj = b1[o0+j];
        #pragma unroll
        for (int i = 0; i < 8; i++) acc[i][j] = bj;
    }
    for (int c = 0; c < 64; c++) {
        float4 xa = *(const float4*)&xs[c*XS_PAD + r0];
        float4 xc = *(const float4*)&xs[c*XS_PAD + r0 + 4];
        float4 wa = *(const float4*)&Wt[c*64 + o0];
        float4 wb = *(const float4*)&Wt[c*64 + o0 + 4];
        float xr[8] = {xa.x,xa.y,xa.z,xa.w,xc.x,xc.y,xc.z,xc.w};
        float wr[8] = {wa.x,wa.y,wa.z,wa.w,wb.x,wb.y,wb.z,wb.w};
        #pragma unroll
        for (int i = 0; i < 8; i++)
            #pragma unroll
            for (int j = 0; j < 8; j++) acc[i][j] = fmaf(xr[i], wr[j], acc[i][j]);
    }
    #pragma unroll
    for (int i = 0; i < 8; i++) {
        size_t base = ((size_t)(blk*128 + r0 + i))*64 + o0;
        *(float4*)&g_y1[base]   = make_float4(acc[i][0],acc[i][1],acc[i][2],acc[i][3]);
        *(float4*)&g_y1[base+4] = make_float4(acc[i][4],acc[i][5],acc[i][6],acc[i][7]);
    }
    #pragma unroll
    for (int j = 0; j < 8; j++) {
        float s = 0.0f, s2 = 0.0f;
        #pragma unroll
        for (int i = 0; i < 8; i++) { s += acc[i][j]; s2 = fmaf(acc[i][j], acc[i][j], s2); }
        #pragma unroll
        for (int off = 8; off; off >>= 1) {
            s  += __shfl_down_sync(0xffffffffu, s,  off, 16);
            s2 += __shfl_down_sync(0xffffffffu, s2, off, 16);
        }
        if ((t & 15) == 0) {
            g_part[(size_t)(o0+j)*8192 + blk]       = (double)s;
            g_part[(size_t)(128+o0+j)*8192 + blk]   = (double)s2;
        }
    }
}

// ---------------- layer2: BN1+ReLU, GEMM 128x64x128, min/max over K + partials (no y2 store) ----------------
__global__ void __launch_bounds__(256, 2) k_layer2(const float* __restrict__ W2,
                                                   const float* __restrict__ b2) {
    extern __shared__ float sm[];
    float* xs  = sm;                   // [64][XS_PAD]
    float* Wt  = sm + 64*XS_PAD;       // [64][128]
    float* ssc = Wt + 8192;
    float* ssh = ssc + 64;
    const int t = threadIdx.x;
    const int blk = blockIdx.x;
    for (int i = t; i < 8192; i += 256) Wt[i] = W2[(i & 127)*64 + (i >> 7)];
    if (t < 64) { ssc[t] = g_scale[128+t]; ssh[t] = g_shift[128+t]; }
    __syncthreads();
    const float4* y1v = (const float4*)g_y1;
    #pragma unroll
    for (int jj = 0; jj < 8; jj++) {
        int idx = t + jj*256;
        int r = idx >> 4, c4 = idx & 15;
        float4 v = y1v[(size_t)(blk*128 + r)*16 + c4];
        float pv[4] = {v.x, v.y, v.z, v.w};
        #pragma unroll
        for (int k2 = 0; k2 < 4; k2++) {
            int c = c4*4 + k2;
            xs[c*XS_PAD + r] = fmaxf(fmaf(ssc[c], pv[k2], ssh[c]), 0.0f);
        }
    }
    __syncthreads();
    const int r0 = (t & 15)*8, o0 = (t >> 4)*8;
    float acc[8][8];
    #pragma unroll
    for (int j = 0; j < 8; j++) {
        float bj = b2[o0+j];
        #pragma unroll
        for (int i = 0; i < 8; i++) acc[i][j] = bj;
    }
    for (int c = 0; c < 64; c++) {
        float4 xa = *(const float4*)&xs[c*XS_PAD + r0];
        float4 xc = *(const float4*)&xs[c*XS_PAD + r0 + 4];
        float4 wa = *(const float4*)&Wt[c*128 + o0];
        float4 wb = *(const float4*)&Wt[c*128 + o0 + 4];
        float xr[8] = {xa.x,xa.y,xa.z,xa.w,xc.x,xc.y,xc.z,xc.w};
        float wr[8] = {wa.x,wa.y,wa.z,wa.w,wb.x,wb.y,wb.z,wb.w};
        #pragma unroll
        for (int i = 0; i < 8; i++)
            #pragma unroll
            for (int j = 0; j < 8; j++) acc[i][j] = fmaf(xr[i], wr[j], acc[i][j]);
    }
    #pragma unroll
    for (int j = 0; j < 8; j++) {
        float s = 0.0f, s2 = 0.0f;
        #pragma unroll
        for (int i = 0; i < 8; i++) { s += acc[i][j]; s2 = fmaf(acc[i][j], acc[i][j], s2); }
        #pragma unroll
        for (int off = 8; off; off >>= 1) {
            s  += __shfl_down_sync(0xffffffffu, s,  off, 16);
            s2 += __shfl_down_sync(0xffffffffu, s2, off, 16);
        }
        if ((t & 15) == 0) {
            g_part[(size_t)(o0+j)*8192 + blk]     = (double)s;
            g_part[(size_t)(128+o0+j)*8192 + blk] = (double)s2;
        }
        // min/max over this query's 32 K-rows (4 row-groups of 8)
        float mx = acc[0][j], mn = acc[0][j];
        #pragma unroll
        for (int i = 1; i < 8; i++) { mx = fmaxf(mx, acc[i][j]); mn = fminf(mn, acc[i][j]); }
        #pragma unroll
        for (int off = 2; off; off >>= 1) {
            mx = fmaxf(mx, __shfl_down_sync(0xffffffffu, mx, off, 4));
            mn = fminf(mn, __shfl_down_sync(0xffffffffu, mn, off, 4));
        }
        if ((t & 3) == 0) {
            int qg = blk*4 + ((t & 15) >> 2);
            g_maxv[(size_t)qg*128 + o0 + j] = mx;
            g_minv[(size_t)qg*128 + o0 + j] = mn;
        }
    }
}

// ---------------- final: BN2+ReLU fused max-pool from min/max ----------------
__global__ void __launch_bounds__(256) k_maxpool(float* __restrict__ out) {
    int i = blockIdx.x*256 + threadIdx.x;
    int o = i & 127;
    float sc = g_scale[256+o], sh = g_shift[256+o];
    float v = (sc >= 0.0f) ? g_maxv[i] : g_minv[i];
    out[OUT_PTS + i] = fmaxf(fmaf(sc, v, sh), 0.0f);
}

// ---------------- launch ----------------
extern "C" void kernel_launch(void* const* d_in, const int* in_sizes, int n_in,
                              void* d_out, int out_size) {
    (void)in_sizes; (void)n_in; (void)out_size;
    const float* xyz    = (const float*)d_in[0];
    const float* points = (const float*)d_in[1];
    const float* W0  = (const float*)d_in[2];
    const float* b0  = (const float*)d_in[3];
    const float* g0  = (const float*)d_in[4];
    const float* bt0 = (const float*)d_in[5];
    const float* W1  = (const float*)d_in[6];
    const float* b1  = (const float*)d_in[7];
    const float* g1  = (const float*)d_in[8];
    const float* bt1 = (const float*)d_in[9];
    const float* W2  = (const float*)d_in[10];
    const float* b2  = (const float*)d_in[11];
    const float* g2  = (const float*)d_in[12];
    const float* bt2 = (const float*)d_in[13];
    float* out = (float*)d_out;

    const int SM_PF = (64*XS_PAD + 64*64) * 4;
    const int SM_L1 = (64*XS_PAD + 64*64 + 6*64) * 4;
    const int SM_L2 = (64*XS_PAD + 64*128 + 2*64) * 4;
    cudaFuncSetAttribute(k_pf,     cudaFuncAttributeMaxDynamicSharedMemorySize, SM_PF);
    cudaFuncSetAttribute(k_layer1, cudaFuncAttributeMaxDynamicSharedMemorySize, SM_L1);
    cudaFuncSetAttribute(k_layer2, cudaFuncAttributeMaxDynamicSharedMemorySize, SM_L2);

    k_prep<<<(NP + 255)/256, 256>>>(xyz);
    k_pf<<<NP/128, 128, SM_PF>>>(points, W0);
    k_fps<<<Bq, 512>>>(xyz, out);
    k_ball<<<NQ, 128>>>(xyz);

    k_l0stats<<<NEq/256, 256>>>(xyz, W0, b0);
    k_fin<<<64, 256>>>(g0, bt0, 0, NEq/256);
    k_layer1<<<NEq/128, 128, SM_L1>>>(xyz, W0, b0, W1, b1);
    k_fin<<<64, 256>>>(g1, bt1, 128, NEq/128);
    k_layer2<<<NEq/128, 256, SM_L2>>>(W2, b2);
    k_fin<<<128, 256>>>(g2, bt2, 256, NEq/128);
    k_maxpool<<<NQ*128/256, 256>>>(out);
}